// round 2
// baseline (speedup 1.0000x reference)
#include <cuda_runtime.h>
#include <cuda_bf16.h>

// ---------------------------------------------------------------------------
// TSGCN: out[b,n,o] = sum_{k,i} xg_k[b,n,i] * W[n,k,i,o] + bias[n,o]
//                   + sum_i xw[b,n,i] * Wwin[n,i,o]
// with xg_0 = x, xg_1 = A x, xg_2 = 2 A (A x) - x,
//      A = softmax(relu(E E^T), rows),
//      W[n,k,i,o] = sum_d E[n,d] wp[d,k,i,o], etc.
//
// Shapes: B=32, N=4096, Cin=16, Cout=64, EMB=16, K=3, WIN=12.
// ---------------------------------------------------------------------------

#define NN   4096      // nodes
#define BB   32        // batch
#define CIN  16
#define COUT 64
#define EMB  16
#define WIN  12
#define BC   (BB*CIN)  // 512 : columns of the "applied" matrices

// ---- scratch (static device memory; no allocations allowed) ----
__device__ __align__(16) float g_A  [NN*NN];   // unnormalized exp(relu(E E^T) - 10)
__device__ __align__(16) float g_inv[NN];      // 1 / row sums
__device__ __align__(16) float g_Xt [NN*BC];   // Xt[m][b*16+c] = x[b][m][c]
__device__ __align__(16) float g_Y1 [NN*BC];   // A @ Xt   (normalized)
__device__ __align__(16) float g_Y2 [NN*BC];   // 2 A @ Y1 - Xt
__device__ __align__(16) float g_Xw [NN*BC];   // time-mixed window, same layout as Xt

// ---------------------------------------------------------------------------
// Kernel 1: build unnormalized A + row-sum reciprocals.
// One block = 8 rows of A, full 4096 columns. Deterministic block reduction.
// ---------------------------------------------------------------------------
__global__ __launch_bounds__(256) void k_build_A(const float* __restrict__ E)
{
    const int tid = threadIdx.x;
    const int n0  = blockIdx.x * 8;

    __shared__ float es[8][EMB];
    __shared__ float red[256];

    if (tid < 8 * EMB) es[tid >> 4][tid & 15] = E[n0 * EMB + tid];
    __syncthreads();

    float sum[8];
#pragma unroll
    for (int r = 0; r < 8; r++) sum[r] = 0.f;

    for (int m = tid; m < NN; m += 256) {
        const float4* em = (const float4*)&E[m * EMB];
        float4 e0 = em[0], e1 = em[1], e2 = em[2], e3 = em[3];
#pragma unroll
        for (int r = 0; r < 8; r++) {
            float d =
                es[r][0]  * e0.x + es[r][1]  * e0.y + es[r][2]  * e0.z + es[r][3]  * e0.w +
                es[r][4]  * e1.x + es[r][5]  * e1.y + es[r][6]  * e1.z + es[r][7]  * e1.w +
                es[r][8]  * e2.x + es[r][9]  * e2.y + es[r][10] * e2.z + es[r][11] * e2.w +
                es[r][12] * e3.x + es[r][13] * e3.y + es[r][14] * e3.z + es[r][15] * e3.w;
            // relu then exp; fixed shift -10 (softmax is shift invariant, avoids overflow)
            float u = __expf(fmaxf(d, 0.f) - 10.f);
            g_A[(n0 + r) * NN + m] = u;
            sum[r] += u;
        }
    }

    // deterministic tree reduction per row
#pragma unroll
    for (int r = 0; r < 8; r++) {
        red[tid] = sum[r];
        __syncthreads();
        for (int s = 128; s > 0; s >>= 1) {
            if (tid < s) red[tid] += red[tid + s];
            __syncthreads();
        }
        if (tid == 0) g_inv[n0 + r] = 1.0f / red[0];
        __syncthreads();
    }
}

// ---------------------------------------------------------------------------
// Kernel 2: transpose x [B,N,Cin] -> Xt [N, B*Cin]
// ---------------------------------------------------------------------------
__global__ __launch_bounds__(256) void k_prep_xt(const float* __restrict__ x)
{
    int idx = blockIdx.x * 256 + threadIdx.x;     // over B*N = 131072
    int b = idx >> 12;
    int m = idx & (NN - 1);
    const float4* src = (const float4*)&x[idx * CIN];
    float4 v0 = src[0], v1 = src[1], v2 = src[2], v3 = src[3];
    float4* dst = (float4*)&g_Xt[m * BC + b * CIN];
    dst[0] = v0; dst[1] = v1; dst[2] = v2; dst[3] = v3;
}

// ---------------------------------------------------------------------------
// Kernel 3: window time-mix: Xw[n][b*16+c] = sum_t T[t] * xw[b][t][n][c]
// ---------------------------------------------------------------------------
__global__ __launch_bounds__(256) void k_prep_xw(const float* __restrict__ xw,
                                                 const float* __restrict__ T)
{
    int idx = blockIdx.x * 256 + threadIdx.x;     // over B*N
    int b = idx >> 12;
    int n = idx & (NN - 1);

    float tv[WIN];
#pragma unroll
    for (int t = 0; t < WIN; t++) tv[t] = __ldg(&T[t]);

    float4 a0 = {0,0,0,0}, a1 = {0,0,0,0}, a2 = {0,0,0,0}, a3 = {0,0,0,0};
#pragma unroll
    for (int t = 0; t < WIN; t++) {
        const float4* p = (const float4*)&xw[(((b * WIN + t) << 12) + n) * CIN];
        float4 v0 = p[0], v1 = p[1], v2 = p[2], v3 = p[3];
        float s = tv[t];
        a0.x += s*v0.x; a0.y += s*v0.y; a0.z += s*v0.z; a0.w += s*v0.w;
        a1.x += s*v1.x; a1.y += s*v1.y; a1.z += s*v1.z; a1.w += s*v1.w;
        a2.x += s*v2.x; a2.y += s*v2.y; a2.z += s*v2.z; a2.w += s*v2.w;
        a3.x += s*v3.x; a3.y += s*v3.y; a3.z += s*v3.z; a3.w += s*v3.w;
    }
    float4* dst = (float4*)&g_Xw[n * BC + b * CIN];
    dst[0] = a0; dst[1] = a1; dst[2] = a2; dst[3] = a3;
}

// ---------------------------------------------------------------------------
// Kernel 4: SGEMM  C = rowscale[n]*fac*(U @ Bsrc)  (+ mode1: - Xt)
//   mode 0:  Y1 = inv_s * (U @ Xt)
//   mode 1:  Y2 = 2*inv_s * (U @ Y1) - Xt
// M=4096, N=512, K=4096.  BM=128 BN=64 BK=16, 256 thr, 8x4 per-thread tile,
// double-buffered shared memory.
// ---------------------------------------------------------------------------
#define BM 128
#define BN 64
#define BK 16

__global__ __launch_bounds__(256) void k_sgemm(int mode)
{
    const float* __restrict__ Ap = g_A;
    const float* __restrict__ Bp = (mode == 0) ? g_Xt : g_Y1;
    float*       Cp              = (mode == 0) ? g_Y1 : g_Y2;
    const float  fac             = (mode == 0) ? 1.0f : 2.0f;

    __shared__ __align__(16) float As[2][BK][BM];
    __shared__ __align__(16) float Bs[2][BK][BN];

    const int tid = threadIdx.x;
    const int tx  = tid & 15;      // col group (4 cols each)
    const int ty  = tid >> 4;      // row group (8 rows each)
    const int m0  = blockIdx.y * BM;
    const int j0  = blockIdx.x * BN;

    // global->reg staging
    float4 pa0, pa1, pb;
    const int q0 = tid, q1 = tid + 256;
    const int ar0 = q0 >> 2, ak0 = (q0 & 3) << 2;
    const int ar1 = q1 >> 2, ak1 = (q1 & 3) << 2;
    const int br  = tid >> 4, bc4 = (tid & 15) << 2;

    float acc[8][4];
#pragma unroll
    for (int i = 0; i < 8; i++)
#pragma unroll
        for (int j = 0; j < 4; j++) acc[i][j] = 0.f;

    // prologue: tile 0
    pa0 = *(const float4*)&Ap[(m0 + ar0) * NN + ak0];
    pa1 = *(const float4*)&Ap[(m0 + ar1) * NN + ak1];
    pb  = *(const float4*)&Bp[br * BC + j0 + bc4];
    As[0][ak0+0][ar0]=pa0.x; As[0][ak0+1][ar0]=pa0.y; As[0][ak0+2][ar0]=pa0.z; As[0][ak0+3][ar0]=pa0.w;
    As[0][ak1+0][ar1]=pa1.x; As[0][ak1+1][ar1]=pa1.y; As[0][ak1+2][ar1]=pa1.z; As[0][ak1+3][ar1]=pa1.w;
    *(float4*)&Bs[0][br][bc4] = pb;
    __syncthreads();

    const int KT = NN / BK;   // 256
    for (int kt = 0; kt < KT; ++kt) {
        const int cur = kt & 1, nxt = cur ^ 1;
        if (kt + 1 < KT) {
            const int k0 = (kt + 1) * BK;
            pa0 = *(const float4*)&Ap[(m0 + ar0) * NN + k0 + ak0];
            pa1 = *(const float4*)&Ap[(m0 + ar1) * NN + k0 + ak1];
            pb  = *(const float4*)&Bp[(k0 + br) * BC + j0 + bc4];
        }
#pragma unroll
        for (int kk = 0; kk < BK; kk++) {
            float4 a0 = *(const float4*)&As[cur][kk][ty * 8];
            float4 a1 = *(const float4*)&As[cur][kk][ty * 8 + 4];
            float4 b0 = *(const float4*)&Bs[cur][kk][tx * 4];
            float av[8] = {a0.x,a0.y,a0.z,a0.w,a1.x,a1.y,a1.z,a1.w};
            float bv[4] = {b0.x,b0.y,b0.z,b0.w};
#pragma unroll
            for (int i = 0; i < 8; i++)
#pragma unroll
                for (int j = 0; j < 4; j++)
                    acc[i][j] += av[i] * bv[j];
        }
        if (kt + 1 < KT) {
            As[nxt][ak0+0][ar0]=pa0.x; As[nxt][ak0+1][ar0]=pa0.y; As[nxt][ak0+2][ar0]=pa0.z; As[nxt][ak0+3][ar0]=pa0.w;
            As[nxt][ak1+0][ar1]=pa1.x; As[nxt][ak1+1][ar1]=pa1.y; As[nxt][ak1+2][ar1]=pa1.z; As[nxt][ak1+3][ar1]=pa1.w;
            *(float4*)&Bs[nxt][br][bc4] = pb;
        }
        __syncthreads();
    }

    // epilogue: row scale (+ optional -Xt)
#pragma unroll
    for (int i = 0; i < 8; i++) {
        const int row = m0 + ty * 8 + i;
        const float s = g_inv[row] * fac;
        float4 r;
        r.x = s * acc[i][0]; r.y = s * acc[i][1];
        r.z = s * acc[i][2]; r.w = s * acc[i][3];
        if (mode == 1) {
            float4 ad = *(const float4*)&g_Xt[row * BC + j0 + tx * 4];
            r.x -= ad.x; r.y -= ad.y; r.z -= ad.z; r.w -= ad.w;
        }
        *(float4*)&Cp[row * BC + j0 + tx * 4] = r;
    }
}

// ---------------------------------------------------------------------------
// Kernel 5: per-node epilogue. One block per node n.
//   Wall[r][o], r = k*16+i (k<3) from weights_pool, r = 48+i from weights_window.
//   V[b][r]    = {Xt, Y1, Y2, Xw}[n][b*16+i].
//   out[b,n,o] = bias[n,o] + sum_r V[b][r]*Wall[r][o]
// ---------------------------------------------------------------------------
__global__ __launch_bounds__(256) void k_epilogue(const float* __restrict__ E,
                                                  const float* __restrict__ wp,
                                                  const float* __restrict__ ww,
                                                  const float* __restrict__ bp,
                                                  float* __restrict__ out)
{
    const int n   = blockIdx.x;
    const int tid = threadIdx.x;

    __shared__ float e_s[EMB];
    __shared__ __align__(16) float Wall[64][64];
    __shared__ __align__(16) float Vs[32][64];
    __shared__ float bias_s[64];

    if (tid < EMB) e_s[tid] = E[n * EMB + tid];
    __syncthreads();

    // generate per-node weights
    for (int idx = tid; idx < 64 * 64; idx += 256) {
        const int r = idx >> 6, o = idx & 63;
        float acc = 0.f;
        if (r < 48) {
            const int k = r >> 4, i = r & 15;
#pragma unroll
            for (int d = 0; d < EMB; d++)
                acc += e_s[d] * wp[((d * 3 + k) * 16 + i) * 64 + o];
        } else {
            const int i = r - 48;
#pragma unroll
            for (int d = 0; d < EMB; d++)
                acc += e_s[d] * ww[(d * 16 + i) * 64 + o];
        }
        Wall[r][o] = acc;
    }
    if (tid < 64) {
        float acc = 0.f;
#pragma unroll
        for (int d = 0; d < EMB; d++) acc += e_s[d] * bp[d * 64 + tid];
        bias_s[tid] = acc;
    }

    // gather per-(b,n) input vectors
    for (int q = tid; q < BC; q += 256) {
        const int b = q >> 4, c = q & 15;
        Vs[b][c]      = g_Xt[n * BC + q];
        Vs[b][16 + c] = g_Y1[n * BC + q];
        Vs[b][32 + c] = g_Y2[n * BC + q];
        Vs[b][48 + c] = g_Xw[n * BC + q];
    }
    __syncthreads();

    // [32 x 64] @ [64 x 64]: each thread owns one output column o, 8 batches
    const int o  = tid & 63;
    const int bb = tid >> 6;           // 0..3
    float wcol[64];
#pragma unroll
    for (int r = 0; r < 64; r++) wcol[r] = Wall[r][o];
    const float bz = bias_s[o];

    for (int bi = 0; bi < 8; bi++) {
        const int b = bb * 8 + bi;
        float acc = bz;
#pragma unroll
        for (int r4 = 0; r4 < 64; r4 += 4) {
            float4 v = *(const float4*)&Vs[b][r4];
            acc += v.x * wcol[r4] + v.y * wcol[r4 + 1] +
                   v.z * wcol[r4 + 2] + v.w * wcol[r4 + 3];
        }
        out[(b * NN + n) * 64 + o] = acc;
    }
}

// ---------------------------------------------------------------------------
extern "C" void kernel_launch(void* const* d_in, const int* in_sizes, int n_in,
                              void* d_out, int out_size)
{
    const float* x   = (const float*)d_in[0];   // [32,4096,16]
    const float* xw  = (const float*)d_in[1];   // [32,12,4096,16]
    const float* E   = (const float*)d_in[2];   // [4096,16]
    const float* wp  = (const float*)d_in[3];   // [16,3,16,64]
    const float* ww  = (const float*)d_in[4];   // [16,16,64]
    const float* bp  = (const float*)d_in[5];   // [16,64]
    const float* T   = (const float*)d_in[6];   // [12]
    float* out = (float*)d_out;                 // [32,4096,64]

    k_build_A<<<NN / 8, 256>>>(E);
    k_prep_xt<<<(BB * NN) / 256, 256>>>(x);
    k_prep_xw<<<(BB * NN) / 256, 256>>>(xw, T);
    k_sgemm<<<dim3(BC / BN, NN / BM), 256>>>(0);   // Y1 = A @ Xt
    k_sgemm<<<dim3(BC / BN, NN / BM), 256>>>(1);   // Y2 = 2 A @ Y1 - Xt
    k_epilogue<<<NN, 256>>>(E, wp, ww, bp, out);
}

// round 4
// speedup vs baseline: 1.8039x; 1.8039x over previous
#include <cuda_runtime.h>
#include <cuda_bf16.h>
#include <cstdint>

// ---------------------------------------------------------------------------
// TSGCN on sm_100 (family-agnostic tensor path: mma.sync bf16 split-2).
//   U = exp(relu(E E^T) - 10) (unnormalized softmax) as bf16 hi/lo pair.
//   Y1 = inv .* (U @ X),  Y2 = 2*inv .* (U @ Y1) - X
//   out[b,n,o] = [X|Y1|Y2|Xw](b,n,:) @ W[n] + bias[n],  W[n] = E[n]·pool
// ---------------------------------------------------------------------------

#define NN   4096
#define BB   32
#define CIN  16
#define EMB  16
#define WIN  12
#define BC   (BB*CIN)      // 512

// ---- static device scratch ----
__device__ __align__(16) __nv_bfloat16 g_Ah[NN*(size_t)NN];
__device__ __align__(16) __nv_bfloat16 g_Al[NN*(size_t)NN];
__device__ float g_inv[NN];
__device__ __align__(16) float         g_Xt  [NN*BC];          // fp32 [k][j]
__device__ __align__(16) __nv_bfloat16 g_XhT [BC*(size_t)NN];  // bf16 [j][k]
__device__ __align__(16) __nv_bfloat16 g_XlT [BC*(size_t)NN];
__device__ __align__(16) float         g_Y1  [NN*BC];
__device__ __align__(16) __nv_bfloat16 g_Y1hT[BC*(size_t)NN];
__device__ __align__(16) __nv_bfloat16 g_Y1lT[BC*(size_t)NN];
__device__ __align__(16) float         g_Y2  [NN*BC];
__device__ __align__(16) float         g_Xw  [NN*BC];
__device__ __align__(16) float         g_W   [NN*(size_t)4096];

// ===========================================================================
// helpers
// ===========================================================================
__device__ __forceinline__ uint32_t u32smem(const void* p){
    uint32_t a;
    asm("{ .reg .u64 t; cvta.to.shared.u64 t, %1; cvt.u32.u64 %0, t; }"
        : "=r"(a) : "l"(p));
    return a;
}
__device__ __forceinline__ void cp16(uint32_t s, const void* g){
    asm volatile("cp.async.cg.shared.global [%0], [%1], 16;\n"
                 :: "r"(s), "l"(g) : "memory");
}
#define CP_COMMIT()  asm volatile("cp.async.commit_group;\n" ::: "memory")
#define CP_WAIT(n)   asm volatile("cp.async.wait_group %0;\n" :: "n"(n) : "memory")

__device__ __forceinline__ void ldm4(uint32_t* r, uint32_t a){
    asm volatile("ldmatrix.sync.aligned.m8n8.x4.shared.b16 {%0,%1,%2,%3}, [%4];\n"
                 : "=r"(r[0]), "=r"(r[1]), "=r"(r[2]), "=r"(r[3]) : "r"(a));
}
__device__ __forceinline__ void mma16816(float* c, const uint32_t* a, const uint32_t* b){
    asm volatile(
        "mma.sync.aligned.m16n8k16.row.col.f32.bf16.bf16.f32 "
        "{%0,%1,%2,%3}, {%4,%5,%6,%7}, {%8,%9}, {%0,%1,%2,%3};\n"
        : "+f"(c[0]), "+f"(c[1]), "+f"(c[2]), "+f"(c[3])
        : "r"(a[0]), "r"(a[1]), "r"(a[2]), "r"(a[3]), "r"(b[0]), "r"(b[1]));
}

// ===========================================================================
// Kernel 1: U = exp(relu(E E^T) - 10) as bf16 hi/lo + row reciprocals
// ===========================================================================
__global__ __launch_bounds__(256) void k_build_A(const float* __restrict__ E)
{
    const int tid = threadIdx.x;
    const int n0  = blockIdx.x * 8;

    __shared__ float es[8][EMB];
    __shared__ float red[256];

    if (tid < 8 * EMB) es[tid >> 4][tid & 15] = E[n0 * EMB + tid];
    __syncthreads();

    float sum[8];
#pragma unroll
    for (int r = 0; r < 8; r++) sum[r] = 0.f;

    for (int m = tid; m < NN; m += 256) {
        const float4* em = (const float4*)&E[m * EMB];
        float4 e0 = em[0], e1 = em[1], e2 = em[2], e3 = em[3];
#pragma unroll
        for (int r = 0; r < 8; r++) {
            float d =
                es[r][0]*e0.x + es[r][1]*e0.y + es[r][2]*e0.z + es[r][3]*e0.w +
                es[r][4]*e1.x + es[r][5]*e1.y + es[r][6]*e1.z + es[r][7]*e1.w +
                es[r][8]*e2.x + es[r][9]*e2.y + es[r][10]*e2.z + es[r][11]*e2.w +
                es[r][12]*e3.x + es[r][13]*e3.y + es[r][14]*e3.z + es[r][15]*e3.w;
            float u = __expf(fmaxf(d, 0.f) - 10.f);
            __nv_bfloat16 h = __float2bfloat16(u);
            size_t o = (size_t)(n0 + r) * NN + m;
            g_Ah[o] = h;
            g_Al[o] = __float2bfloat16(u - __bfloat162float(h));
            sum[r] += u;
        }
    }

#pragma unroll
    for (int r = 0; r < 8; r++) {
        red[tid] = sum[r];
        __syncthreads();
        for (int s = 128; s > 0; s >>= 1) {
            if (tid < s) red[tid] += red[tid + s];
            __syncthreads();
        }
        if (tid == 0) g_inv[n0 + r] = 1.0f / red[0];
        __syncthreads();
    }
}

// ===========================================================================
// Kernel 2: x -> g_Xt (fp32 [k][j]) and g_XhT/g_XlT (bf16 [j][k])
// ===========================================================================
__global__ __launch_bounds__(256) void k_prep_x(const float* __restrict__ x)
{
    const int b = blockIdx.y, m0 = blockIdx.x * 128, tid = threadIdx.x;
    __shared__ float sm[128][17];

    for (int q = tid; q < 2048; q += 256) {
        int i = q >> 4, c = q & 15;
        float v = x[((size_t)b * NN + m0 + i) * CIN + c];
        sm[i][c] = v;
        g_Xt[(m0 + i) * BC + b * CIN + c] = v;
    }
    __syncthreads();
    for (int q = tid; q < 2048; q += 256) {
        int c = q >> 7, i = q & 127;
        float v = sm[i][c];
        __nv_bfloat16 h = __float2bfloat16(v);
        size_t o = (size_t)(b * CIN + c) * NN + m0 + i;
        g_XhT[o] = h;
        g_XlT[o] = __float2bfloat16(v - __bfloat162float(h));
    }
}

// ===========================================================================
// Kernel 3: window time mix
// ===========================================================================
__global__ __launch_bounds__(256) void k_prep_xw(const float* __restrict__ xw,
                                                 const float* __restrict__ T)
{
    int idx = blockIdx.x * 256 + threadIdx.x;
    int b = idx >> 12;
    int n = idx & (NN - 1);

    float tv[WIN];
#pragma unroll
    for (int t = 0; t < WIN; t++) tv[t] = __ldg(&T[t]);

    float4 a0 = {0,0,0,0}, a1 = {0,0,0,0}, a2 = {0,0,0,0}, a3 = {0,0,0,0};
#pragma unroll
    for (int t = 0; t < WIN; t++) {
        const float4* p = (const float4*)&xw[(((size_t)(b * WIN + t) << 12) + n) * CIN];
        float4 v0 = p[0], v1 = p[1], v2 = p[2], v3 = p[3];
        float s = tv[t];
        a0.x += s*v0.x; a0.y += s*v0.y; a0.z += s*v0.z; a0.w += s*v0.w;
        a1.x += s*v1.x; a1.y += s*v1.y; a1.z += s*v1.z; a1.w += s*v1.w;
        a2.x += s*v2.x; a2.y += s*v2.y; a2.z += s*v2.z; a2.w += s*v2.w;
        a3.x += s*v3.x; a3.y += s*v3.y; a3.z += s*v3.z; a3.w += s*v3.w;
    }
    float4* dst = (float4*)&g_Xw[n * BC + b * CIN];
    dst[0] = a0; dst[1] = a1; dst[2] = a2; dst[3] = a3;
}

// ===========================================================================
// Kernel 4: per-node weight generation g_W[n][ro] = sum_d E[n,d]*P[d,ro]
// ===========================================================================
__global__ __launch_bounds__(256) void k_wgen(const float* __restrict__ wp,
                                              const float* __restrict__ ww,
                                              const float* __restrict__ E)
{
    const int ro0 = blockIdx.x * 512, n0 = blockIdx.y * 64, tid = threadIdx.x;
    __shared__ float Ps[16][512];
    __shared__ float Es[64][17];

    for (int q = tid; q < 16 * 512; q += 256) {
        int d = q >> 9, r = q & 511, ro = ro0 + r;
        Ps[d][r] = (ro < 3072) ? wp[d * 3072 + ro] : ww[d * 1024 + (ro - 3072)];
    }
    for (int q = tid; q < 64 * 16; q += 256)
        Es[q >> 4][q & 15] = E[(n0 + (q >> 4)) * EMB + (q & 15)];
    __syncthreads();

    const int r2 = tid * 2;
    float2 pr[16];
#pragma unroll
    for (int d = 0; d < 16; d++) pr[d] = *(const float2*)&Ps[d][r2];

    for (int n = 0; n < 64; n++) {
        float a0 = 0.f, a1 = 0.f;
#pragma unroll
        for (int d = 0; d < 16; d++) {
            float e = Es[n][d];
            a0 += e * pr[d].x;
            a1 += e * pr[d].y;
        }
        float2 v = {a0, a1};
        *(float2*)&g_W[(size_t)(n0 + n) * 4096 + ro0 + r2] = v;
    }
}

// ===========================================================================
// Kernel 5: bf16 split-2 GEMM via mma.sync.m16n8k16.
//   C[4096x512] = U @ B  (3 products: AhBh + AhBl + AlBh), fp32 accum.
//   mode 0: Y1 = inv*C  (+ write Y1hT/Y1lT bf16 transposed)
//   mode 1: Y2 = 2*inv*C - Xt
// Block 256 thr (8 warps, 4x2), tile 128m x 128n, BK=32, double buffer.
// ===========================================================================
#define STR     80                    // smem row pitch bytes: (32+8)*2
#define TILEB   (128*STR)             // 10240 B per tile
#define STAGEB  (4*TILEB)             // Ah | Al | Bh | Bl
#define GSMEM   (2*STAGEB)            // 81920
#define NCHUNK  128                   // 4096 / 32

__device__ __forceinline__ void load_stage(uint32_t st, int c,
        const __nv_bfloat16* __restrict__ Ah, const __nv_bfloat16* __restrict__ Al,
        const __nv_bfloat16* __restrict__ Bh, const __nv_bfloat16* __restrict__ Bl,
        int tid)
{
    const int k0 = c * 32;
#pragma unroll
    for (int rep = 0; rep < 2; rep++) {
        int idx = tid + rep * 256;           // 0..511
        int row = idx >> 2, g = idx & 3;
        uint32_t dst = st + row * STR + g * 16;
        size_t   src = (size_t)row * NN + k0 + g * 8;
        cp16(dst,              Ah + src);
        cp16(dst + 1*TILEB,    Al + src);
        cp16(dst + 2*TILEB,    Bh + src);
        cp16(dst + 3*TILEB,    Bl + src);
    }
    CP_COMMIT();
}

__global__ __launch_bounds__(256, 1) void k_gemm(int mode)
{
    extern __shared__ char smem[];
    const uint32_t sb0 = u32smem(smem);

    const int tid  = threadIdx.x;
    const int wid  = tid >> 5, lane = tid & 31;
    const int m0   = blockIdx.y * 128, j0 = blockIdx.x * 128;
    const int wm   = (wid & 3) * 32;       // warp m offset in tile
    const int wn   = (wid >> 2) * 64;      // warp n offset in tile

    const __nv_bfloat16* Ahp = g_Ah + (size_t)m0 * NN;
    const __nv_bfloat16* Alp = g_Al + (size_t)m0 * NN;
    const __nv_bfloat16* Bhp = (mode ? g_Y1hT : g_XhT) + (size_t)j0 * NN;
    const __nv_bfloat16* Blp = (mode ? g_Y1lT : g_XlT) + (size_t)j0 * NN;

    float c[2][8][4];
#pragma unroll
    for (int i = 0; i < 2; i++)
#pragma unroll
        for (int f = 0; f < 8; f++)
#pragma unroll
            for (int q = 0; q < 4; q++) c[i][f][q] = 0.f;

    // ldmatrix lane -> address components
    const int arow  = lane & 15;             // A: row within 16-row frag
    const int acolb = (lane >> 4) * 16;      // A: +8 cols (bytes) for hi half
    const int brow  = (lane & 7) + ((lane >> 4) << 3);   // B: n within 16
    const int bcolb = ((lane >> 3) & 1) * 16;            // B: +8 k (bytes)

    load_stage(sb0, 0, Ahp, Alp, Bhp, Blp, tid);

    for (int ck = 0; ck < NCHUNK; ck++) {
        if (ck + 1 < NCHUNK)
            load_stage(sb0 + ((ck + 1) & 1) * STAGEB, ck + 1, Ahp, Alp, Bhp, Blp, tid);
        if (ck + 1 < NCHUNK) CP_WAIT(1); else CP_WAIT(0);
        __syncthreads();

        const uint32_t sb = sb0 + (ck & 1) * STAGEB;
#pragma unroll
        for (int kk = 0; kk < 2; kk++) {     // two k16 steps per 32-chunk
            const int kb = kk * 32;          // byte offset of k16 step
            uint32_t ah[2][4], al[2][4], bh[4][4], bl[4][4];
#pragma unroll
            for (int i = 0; i < 2; i++) {
                uint32_t a = sb + (wm + i * 16 + arow) * STR + kb + acolb;
                ldm4(ah[i], a);
                ldm4(al[i], a + 1*TILEB);
            }
#pragma unroll
            for (int ng = 0; ng < 4; ng++) {
                uint32_t a = sb + 2*TILEB + (wn + ng * 16 + brow) * STR + kb + bcolb;
                ldm4(bh[ng], a);
                ldm4(bl[ng], a + TILEB);
            }
#pragma unroll
            for (int i = 0; i < 2; i++)
#pragma unroll
                for (int ng = 0; ng < 4; ng++) {
                    mma16816(c[i][ng*2],   ah[i], bh[ng]);
                    mma16816(c[i][ng*2+1], ah[i], bh[ng]+2);
                    mma16816(c[i][ng*2],   ah[i], bl[ng]);
                    mma16816(c[i][ng*2+1], ah[i], bl[ng]+2);
                    mma16816(c[i][ng*2],   al[i], bh[ng]);
                    mma16816(c[i][ng*2+1], al[i], bh[ng]+2);
                }
        }
        __syncthreads();
    }

    // ---- epilogue ----
    const int l4 = lane >> 2, l2 = (lane & 3) * 2;
#pragma unroll
    for (int i = 0; i < 2; i++) {
        const int mr0 = m0 + wm + i * 16 + l4;
        const int mr1 = mr0 + 8;
        const float s0 = (mode ? 2.f : 1.f) * g_inv[mr0];
        const float s1 = (mode ? 2.f : 1.f) * g_inv[mr1];
#pragma unroll
        for (int f = 0; f < 8; f++) {
            const int j = j0 + wn + (f >> 1) * 16 + (f & 1) * 8 + l2;
            float y00 = s0 * c[i][f][0], y01 = s0 * c[i][f][1];
            float y10 = s1 * c[i][f][2], y11 = s1 * c[i][f][3];
            if (mode == 0) {
                float2 v0 = {y00, y01}, v1 = {y10, y11};
                *(float2*)&g_Y1[mr0 * BC + j] = v0;
                *(float2*)&g_Y1[mr1 * BC + j] = v1;
                __nv_bfloat16 h;
                h = __float2bfloat16(y00);
                g_Y1hT[(size_t)j * NN + mr0] = h;
                g_Y1lT[(size_t)j * NN + mr0] = __float2bfloat16(y00 - __bfloat162float(h));
                h = __float2bfloat16(y01);
                g_Y1hT[(size_t)(j+1) * NN + mr0] = h;
                g_Y1lT[(size_t)(j+1) * NN + mr0] = __float2bfloat16(y01 - __bfloat162float(h));
                h = __float2bfloat16(y10);
                g_Y1hT[(size_t)j * NN + mr1] = h;
                g_Y1lT[(size_t)j * NN + mr1] = __float2bfloat16(y10 - __bfloat162float(h));
                h = __float2bfloat16(y11);
                g_Y1hT[(size_t)(j+1) * NN + mr1] = h;
                g_Y1lT[(size_t)(j+1) * NN + mr1] = __float2bfloat16(y11 - __bfloat162float(h));
            } else {
                float2 x0 = *(const float2*)&g_Xt[mr0 * BC + j];
                float2 x1 = *(const float2*)&g_Xt[mr1 * BC + j];
                float2 v0 = {y00 - x0.x, y01 - x0.y};
                float2 v1 = {y10 - x1.x, y11 - x1.y};
                *(float2*)&g_Y2[mr0 * BC + j] = v0;
                *(float2*)&g_Y2[mr1 * BC + j] = v1;
            }
        }
    }
}

// ===========================================================================
// Kernel 6: final per-node epilogue
// ===========================================================================
__global__ __launch_bounds__(256) void k_epilogue(const float* __restrict__ E,
                                                  const float* __restrict__ bp,
                                                  float* __restrict__ out)
{
    const int n = blockIdx.x;
    const int tid = threadIdx.x;

    __shared__ float e_s[EMB];
    __shared__ __align__(16) float Wall[4096];
    __shared__ __align__(16) float Vs[32][64];
    __shared__ float bias_s[64];

    if (tid < EMB) e_s[tid] = E[n * EMB + tid];

    const float4* Wn = (const float4*)(g_W + (size_t)n * 4096);
    for (int q = tid; q < 1024; q += 256) ((float4*)Wall)[q] = Wn[q];

    for (int q = tid; q < BC; q += 256) {
        int b = q >> 4, c = q & 15;
        Vs[b][c]      = g_Xt[n * BC + q];
        Vs[b][16 + c] = g_Y1[n * BC + q];
        Vs[b][32 + c] = g_Y2[n * BC + q];
        Vs[b][48 + c] = g_Xw[n * BC + q];
    }
    __syncthreads();
    if (tid < 64) {
        float acc = 0.f;
#pragma unroll
        for (int d = 0; d < EMB; d++) acc += e_s[d] * bp[d * 64 + tid];
        bias_s[tid] = acc;
    }
    __syncthreads();

    const int o  = tid & 63;
    const int bb = tid >> 6;
    float wcol[64];
#pragma unroll
    for (int r = 0; r < 64; r++) wcol[r] = Wall[r * 64 + o];
    const float bz = bias_s[o];

    for (int bi = 0; bi < 8; bi++) {
        const int b = bb * 8 + bi;
        float acc = bz;
#pragma unroll
        for (int r4 = 0; r4 < 64; r4 += 4) {
            float4 v = *(const float4*)&Vs[b][r4];
            acc += v.x * wcol[r4] + v.y * wcol[r4+1] + v.z * wcol[r4+2] + v.w * wcol[r4+3];
        }
        out[((size_t)b * NN + n) * 64 + o] = acc;
    }
}

// ===========================================================================
extern "C" void kernel_launch(void* const* d_in, const int* in_sizes, int n_in,
                              void* d_out, int out_size)
{
    const float* x   = (const float*)d_in[0];
    const float* xw  = (const float*)d_in[1];
    const float* E   = (const float*)d_in[2];
    const float* wp  = (const float*)d_in[3];
    const float* ww  = (const float*)d_in[4];
    const float* bp  = (const float*)d_in[5];
    const float* T   = (const float*)d_in[6];
    float* out = (float*)d_out;

    cudaFuncSetAttribute(k_gemm, cudaFuncAttributeMaxDynamicSharedMemorySize, GSMEM);

    k_build_A<<<NN / 8, 256>>>(E);
    k_prep_x <<<dim3(32, 32), 256>>>(x);
    k_prep_xw<<<(BB * NN) / 256, 256>>>(xw, T);
    k_wgen   <<<dim3(8, 64), 256>>>(wp, ww, E);
    k_gemm   <<<dim3(BC / 128, NN / 128), 256, GSMEM>>>(0);   // Y1
    k_gemm   <<<dim3(BC / 128, NN / 128), 256, GSMEM>>>(1);   // Y2
    k_epilogue<<<NN, 256>>>(E, bp, out);
}